// round 15
// baseline (speedup 1.0000x reference)
#include <cuda_runtime.h>
#include <cuda_bf16.h>
#include <cstdint>
#include <cstddef>

// ---------------------------------------------------------------------------
// STDP delta_w:
//   delta_w = sum_t O_t^T P_t  -  s[:,None] * W
// GEMM: K = T*B = 1024 (k = b*64 + t), M = POST = 4096, N = PRE = 4096.
// R15: fused launch with PER-BATCH gating. GEMM chunk c consumes exactly
// prep batch c (KC == T_STEPS), so 16 counters let the mainloop start after
// ~1/16 of prep and hide the rest behind compute. R14's coarse gate (wait
// for ALL prep) serialized and regressed; this is the fix.
// Mainloop = R13 (plateau-proven 103.5us GEMM). s-reduce moved post-mainloop.
// ---------------------------------------------------------------------------

namespace {
constexpr int T_STEPS = 64;
constexpr int BATCH   = 16;
constexpr int PRE_N   = 4096;
constexpr int POST_N  = 4096;
constexpr int KDIM    = T_STEPS * BATCH;  // 1024

constexpr int TM = 128;
constexpr int TN = 128;
constexpr int KC = 64;                       // == T_STEPS: chunk c <-> batch c
constexpr int NCHUNK  = KDIM / KC;           // 16
constexpr int NSTAGES = 3;
constexpr int A_STAGE_BYTES = TM * 128;      // 16384
constexpr int B_STAGE_BYTES = TN * 128;      // 16384
constexpr int STAGE_BYTES   = A_STAGE_BYTES + B_STAGE_BYTES;   // 32768
constexpr int S_OFF         = NSTAGES * STAGE_BYTES;           // 98304
constexpr int SMEM_TOTAL    = S_OFF + TM * 4;                  // +512 for s[]

constexpr int NB_PRE  = (BATCH * PRE_N)  / 256;  // 256 (16 blocks per batch)
constexpr int NB_POST = (BATCH * POST_N) / 256;  // 256 (16 blocks per batch)
constexpr int NB_PREP = NB_PRE + NB_POST;        // 512
constexpr int NGEMM   = (PRE_N / TN) * (POST_N / TM);  // 1024
constexpr int NBLOCKS = NB_PREP + NGEMM;         // 1536
constexpr unsigned int CTR_TARGET = 32;          // 16 pre + 16 post blocks
}

// Scratch (device globals: allocation-free rule)
__device__ __nv_bfloat16 g_A[POST_N * KDIM];   // out_spikes^T bf16 [post][k]
__device__ __nv_bfloat16 g_B[PRE_N * KDIM];    // trace_pre^T bf16 [pre][k]
__device__ float g_spart[BATCH * POST_N];
__device__ unsigned int g_ctr[BATCH];          // per-batch prep completion
__device__ unsigned int g_pass;                // GEMM finishers (for reset)

// ---------------------------------------------------------------------------
// PTX helpers
// ---------------------------------------------------------------------------
__device__ __forceinline__ void cp_async16(unsigned int saddr, const void* gptr) {
    asm volatile("cp.async.cg.shared.global [%0], [%1], 16;"
                 :: "r"(saddr), "l"(gptr) : "memory");
}

__device__ __forceinline__ void l2_prefetch(const void* gptr) {
    asm volatile("prefetch.global.L2 [%0];" :: "l"(gptr));
}

__device__ __forceinline__ void ldsm_x4(unsigned int& r0, unsigned int& r1,
                                        unsigned int& r2, unsigned int& r3,
                                        unsigned int addr) {
    asm volatile("ldmatrix.sync.aligned.m8n8.x4.shared.b16 {%0,%1,%2,%3}, [%4];"
                 : "=r"(r0), "=r"(r1), "=r"(r2), "=r"(r3) : "r"(addr));
}

__device__ __forceinline__ void mma16816(float* c,
                                         unsigned int a0, unsigned int a1,
                                         unsigned int a2, unsigned int a3,
                                         unsigned int b0, unsigned int b1) {
    asm volatile(
        "mma.sync.aligned.m16n8k16.row.col.f32.bf16.bf16.f32 "
        "{%0,%1,%2,%3}, {%4,%5,%6,%7}, {%8,%9}, {%0,%1,%2,%3};"
        : "+f"(c[0]), "+f"(c[1]), "+f"(c[2]), "+f"(c[3])
        : "r"(a0), "r"(a1), "r"(a2), "r"(a3), "r"(b0), "r"(b1));
}

// per-thread spin until prep batch b is complete (data visible at L2;
// cp.async.cg reads L2 directly, so L2 serialization gives visibility)
__device__ __forceinline__ void gate_wait(int b) {
    const volatile unsigned int* c = (const volatile unsigned int*)&g_ctr[b];
    while (*c < CTR_TARGET) __nanosleep(64);
}

// ---------------------------------------------------------------------------
// Prep work (blocks 0..NB_PREP-1). Block bid covers batch bid>>4.
// ---------------------------------------------------------------------------
__device__ __forceinline__ void prep_pre_block(int bid, const float* __restrict__ in_spikes) {
    int g = bid * 256 + threadIdx.x;
    int p = g & (PRE_N - 1);
    int b = g >> 12;
    const float* src = in_spikes + (size_t)b * PRE_N + p;
    float tp = 0.0f;
    unsigned int packed[T_STEPS / 2];
#pragma unroll
    for (int t2 = 0; t2 < T_STEPS / 2; ++t2) {
        float i0 = src[(size_t)(2 * t2)     * (BATCH * PRE_N)];
        float i1 = src[(size_t)(2 * t2 + 1) * (BATCH * PRE_N)];
        tp = fminf(fmaxf(fmaf(0.5f, tp, i0), 0.0f), 1.0f);
        float v0 = tp;
        tp = fminf(fmaxf(fmaf(0.5f, tp, i1), 0.0f), 1.0f);
        float v1 = tp;
        __nv_bfloat162 h2 = __floats2bfloat162_rn(v0, v1);
        packed[t2] = *reinterpret_cast<unsigned int*>(&h2);
    }
    uint4* dst = reinterpret_cast<uint4*>(g_B + (size_t)p * KDIM + b * T_STEPS);
#pragma unroll
    for (int i = 0; i < 8; ++i)
        dst[i] = make_uint4(packed[4*i+0], packed[4*i+1], packed[4*i+2], packed[4*i+3]);
}

__device__ __forceinline__ void prep_post_block(int bid, const float* __restrict__ out_spikes) {
    int g = bid * 256 + threadIdx.x;
    int q = g & (POST_N - 1);
    int b = g >> 12;
    const float* src = out_spikes + (size_t)b * POST_N + q;
    float tp = 0.0f, sacc = 0.0f;
    unsigned int packed[T_STEPS / 2];
#pragma unroll
    for (int t2 = 0; t2 < T_STEPS / 2; ++t2) {
        float o0 = src[(size_t)(2 * t2)     * (BATCH * POST_N)];
        float o1 = src[(size_t)(2 * t2 + 1) * (BATCH * POST_N)];
        tp = fmaf(0.5f, tp, o0);
        sacc = fmaf(o0, tp, sacc);
        float w0 = o0;
        tp = fmaf(0.5f, tp, o1);
        sacc = fmaf(o1, tp, sacc);
        __nv_bfloat162 h2 = __floats2bfloat162_rn(w0, o1);
        packed[t2] = *reinterpret_cast<unsigned int*>(&h2);
    }
    uint4* dst = reinterpret_cast<uint4*>(g_A + (size_t)q * KDIM + b * T_STEPS);
#pragma unroll
    for (int i = 0; i < 8; ++i)
        dst[i] = make_uint4(packed[4*i+0], packed[4*i+1], packed[4*i+2], packed[4*i+3]);
    g_spart[b * POST_N + q] = sacc;
}

// ---------------------------------------------------------------------------
// Fused kernel.
// ---------------------------------------------------------------------------
__global__ void __launch_bounds__(256, 2) stdp_fused_kernel(
    const float* __restrict__ in_spikes, const float* __restrict__ out_spikes,
    const float* __restrict__ weight, float* __restrict__ out)
{
    extern __shared__ __align__(1024) char smem[];
    const int bid = blockIdx.x;
    const int tid = threadIdx.x;

    // ================= PREP BLOCKS =================
    if (bid < NB_PREP) {
        int batch;
        if (bid < NB_PRE) { prep_pre_block(bid, in_spikes); batch = bid >> 4; }
        else { prep_post_block(bid - NB_PRE, out_spikes); batch = (bid - NB_PRE) >> 4; }
        __threadfence();          // release stores device-wide (to L2)
        __syncthreads();          // all threads' fences done
        if (tid == 0) atomicAdd(&g_ctr[batch], 1u);
        return;
    }

    // ================= GEMM BLOCKS =================
    const unsigned int sbase = (unsigned int)__cvta_generic_to_shared(smem);
    float* s_sm = reinterpret_cast<float*>(smem + S_OFF);
    const int gb  = bid - NB_PREP;
    const int n0  = (gb & 31) * TN;
    const int m0  = (gb >> 5) * TM;
    const int wid = tid >> 5;
    const int lid = tid & 31;

    const int warp_m = wid & 1;   // m offset 0/64
    const int warp_n = wid >> 1;  // n offset 0/32/64/96

    // ---- per-thread load addressing ----
    const int lm = tid >> 3;
    const int k8 = tid & 7;
    const unsigned int sw_base =
        (unsigned int)(lm * 128) + ((unsigned int)(k8 * 16) ^ ((lm & 7) << 4));
    const __nv_bfloat16* pa = g_A + (size_t)(m0 + lm) * KDIM + k8 * 8;
    const __nv_bfloat16* pb = g_B + (size_t)(n0 + lm) * KDIM + k8 * 8;

    auto load_chunk_full = [&](const __nv_bfloat16* a, const __nv_bfloat16* b, int st) {
        const unsigned int sa = sbase + st * STAGE_BYTES + sw_base;
#pragma unroll
        for (int i = 0; i < 4; ++i)
            cp_async16(sa + i * 4096, a + (size_t)i * 32 * KDIM);
        const unsigned int sb = sa + A_STAGE_BYTES;
#pragma unroll
        for (int i = 0; i < 4; ++i)
            cp_async16(sb + i * 4096, b + (size_t)i * 32 * KDIM);
    };

    // ---- ldmatrix lane addressing ----
    const int q  = lid >> 3;
    const int r  = lid & 7;
    const int lrow = (q & 1) * 8 + r;
    const int lkb  = (q >> 1) * 16;
    unsigned int kxor[4];
#pragma unroll
    for (int ks = 0; ks < 4; ++ks)
        kxor[ks] = (unsigned int)((ks * 32 + lkb) ^ (r << 4));
    const unsigned int a_rowbase = (unsigned int)((warp_m * 64 + lrow) * 128);
    const unsigned int b_rowbase = (unsigned int)((warp_n * 32 + lrow) * 128);

    float acc[4][4][4];
#pragma unroll
    for (int mt = 0; mt < 4; ++mt)
#pragma unroll
        for (int nt = 0; nt < 4; ++nt)
#pragma unroll
            for (int j = 0; j < 4; ++j) acc[mt][nt][j] = 0.0f;

    // ---- prologue: gate + load chunks 0,1 ----
    gate_wait(0);
    load_chunk_full(pa, pb, 0);
    asm volatile("cp.async.commit_group;" ::: "memory");
    gate_wait(1);
    load_chunk_full(pa + KC, pb + KC, 1);
    asm volatile("cp.async.commit_group;" ::: "memory");
    pa += 2 * KC; pb += 2 * KC;   // point at chunk 2 (next prefetch)

    // W prefetch base for this warp's epilogue region
    const float* wpf = weight + (size_t)(m0 + warp_m * 64) * PRE_N + n0 + warp_n * 32;

    int st = 0;
    // ---- mainloop ----
    for (int c = 0; c < NCHUNK; ++c) {
        asm volatile("cp.async.wait_group 1;" ::: "memory");
        __syncthreads();   // chunk c visible; all warps done with stage st2

        const unsigned int sa = sbase + st * STAGE_BYTES;
        const unsigned int sb = sa + A_STAGE_BYTES;
        int st2 = st + 2; if (st2 >= NSTAGES) st2 -= NSTAGES;   // stage for c+2
        const unsigned int spa = sbase + st2 * STAGE_BYTES + sw_base;
        const unsigned int spb = spa + A_STAGE_BYTES;
        const bool do_load = (c + 2 < NCHUNK);

        // L2-prefetch 4 rows of this warp's W epilogue tile per chunk
        if (lid < 4)
            l2_prefetch(wpf + (size_t)(c * 4 + lid) * PRE_N);

#pragma unroll
        for (int ks = 0; ks < 4; ++ks) {
            unsigned int af[4][4], bf[2][4];
#pragma unroll
            for (int mt = 0; mt < 4; ++mt)
                ldsm_x4(af[mt][0], af[mt][1], af[mt][2], af[mt][3],
                        sa + a_rowbase + mt * 2048 + kxor[ks]);
#pragma unroll
            for (int nt2 = 0; nt2 < 2; ++nt2)
                ldsm_x4(bf[nt2][0], bf[nt2][1], bf[nt2][2], bf[nt2][3],
                        sb + b_rowbase + nt2 * 2048 + kxor[ks]);

            // gate chunk c+2 (== prep batch c+2), then spread its loads
            if (do_load) {
                if (ks == 0) {
                    gate_wait(c + 2);
                    cp_async16(spa,        pa);
                    cp_async16(spa + 4096, pa + (size_t)32 * KDIM);
                } else if (ks == 1) {
                    cp_async16(spa + 8192,  pa + (size_t)64 * KDIM);
                    cp_async16(spa + 12288, pa + (size_t)96 * KDIM);
                } else if (ks == 2) {
                    cp_async16(spb,        pb);
                    cp_async16(spb + 4096, pb + (size_t)32 * KDIM);
                } else {
                    cp_async16(spb + 8192,  pb + (size_t)64 * KDIM);
                    cp_async16(spb + 12288, pb + (size_t)96 * KDIM);
                }
            }

#pragma unroll
            for (int mt = 0; mt < 4; ++mt)
#pragma unroll
                for (int nt2 = 0; nt2 < 2; ++nt2) {
                    mma16816(acc[mt][2 * nt2],
                             af[mt][0], af[mt][1], af[mt][2], af[mt][3],
                             bf[nt2][0], bf[nt2][2]);
                    mma16816(acc[mt][2 * nt2 + 1],
                             af[mt][0], af[mt][1], af[mt][2], af[mt][3],
                             bf[nt2][1], bf[nt2][3]);
                }
        }
        asm volatile("cp.async.commit_group;" ::: "memory");
        pa += KC; pb += KC;
        if (++st == NSTAGES) st = 0;
    }

    // ---- s reduction (all prep batches done: gated via chunk 15) ----
    if (tid < TM) {
        float sv = 0.0f;
#pragma unroll
        for (int b = 0; b < BATCH; ++b) sv += __ldg(&g_spart[b * POST_N + m0 + tid]);
        s_sm[tid] = sv;
    }
    __syncthreads();

    // ---- fused epilogue: out = acc - s[m] * W[m][n]; s from smem ----
    const int tid4 = lid >> 2;
    const int tp   = lid & 3;
#pragma unroll
    for (int mt = 0; mt < 4; ++mt) {
#pragma unroll
        for (int half = 0; half < 2; ++half) {
            const int lrow_ep = warp_m * 64 + mt * 16 + half * 8 + tid4;
            const int gm = m0 + lrow_ep;
            const float sv = s_sm[lrow_ep];
            const float* wrow = weight + (size_t)gm * PRE_N + n0 + warp_n * 32;
            float* orow       = out    + (size_t)gm * PRE_N + n0 + warp_n * 32;
#pragma unroll
            for (int nt = 0; nt < 4; ++nt) {
                const int col = nt * 8 + 2 * tp;
                float2 w2 = __ldcs(reinterpret_cast<const float2*>(wrow + col));
                float2 o2;
                o2.x = acc[mt][nt][2 * half + 0] - sv * w2.x;
                o2.y = acc[mt][nt][2 * half + 1] - sv * w2.y;
                __stcs(reinterpret_cast<float2*>(orow + col), o2);
            }
        }
    }

    // ---- counter reset for graph replay (last GEMM block) ----
    if (tid == 0) {
        unsigned int p = atomicAdd(&g_pass, 1u);
        if (p == (unsigned int)(NGEMM - 1)) {
#pragma unroll
            for (int i = 0; i < BATCH; ++i) atomicExch(&g_ctr[i], 0u);
            __threadfence();
            atomicExch(&g_pass, 0u);
        }
    }
}

// ---------------------------------------------------------------------------
extern "C" void kernel_launch(void* const* d_in, const int* in_sizes, int n_in,
                              void* d_out, int out_size) {
    (void)in_sizes; (void)n_in; (void)out_size;
    const float* in_spikes  = (const float*)d_in[0];
    const float* out_spikes = (const float*)d_in[1];
    const float* weight     = (const float*)d_in[2];
    float* out = (float*)d_out;

    cudaFuncSetAttribute(stdp_fused_kernel,
                         cudaFuncAttributeMaxDynamicSharedMemorySize, SMEM_TOTAL);

    stdp_fused_kernel<<<NBLOCKS, 256, SMEM_TOTAL>>>(in_spikes, out_spikes, weight, out);
}

// round 16
// speedup vs baseline: 1.1525x; 1.1525x over previous
#include <cuda_runtime.h>
#include <cuda_bf16.h>
#include <cstdint>
#include <cstddef>

// ---------------------------------------------------------------------------
// STDP delta_w:
//   delta_w = sum_t O_t^T P_t  -  s[:,None] * W
// GEMM: K = T*B = 1024, M = POST = 4096, N = PRE = 4096, HMMA mma.sync bf16.
// R16: R13 GEMM untouched (plateau-proven best, 103.5us). Prep vectorized:
// each thread scans TWO adjacent columns with float2 loads (2x bytes/instr,
// 2 independent FMA chains, half the blocks). R13 prep ran at ~4.4TB/s of an
// ~8TB/s chip — instruction-rate bound, not BW bound.
// Fusion abandoned: R14 (coarse gate) and R15 (per-batch gate) both regressed
// via prep/GEMM occupancy mixing.
// ---------------------------------------------------------------------------

namespace {
constexpr int T_STEPS = 64;
constexpr int BATCH   = 16;
constexpr int PRE_N   = 4096;
constexpr int POST_N  = 4096;
constexpr int KDIM    = T_STEPS * BATCH;  // 1024

constexpr int TM = 128;
constexpr int TN = 128;
constexpr int KC = 64;                       // K elems per chunk (128 B rows)
constexpr int NCHUNK  = KDIM / KC;           // 16
constexpr int NSTAGES = 3;
constexpr int A_STAGE_BYTES = TM * 128;      // 16384
constexpr int B_STAGE_BYTES = TN * 128;      // 16384
constexpr int STAGE_BYTES   = A_STAGE_BYTES + B_STAGE_BYTES;   // 32768
constexpr int S_OFF         = NSTAGES * STAGE_BYTES;           // 98304
constexpr int SMEM_TOTAL    = S_OFF + TM * 4;                  // +512 for s[]

// prep: 2 columns per thread
constexpr int NB_PRE  = (BATCH * PRE_N  / 2) / 256;  // 128
constexpr int NB_POST = (BATCH * POST_N / 2) / 256;  // 128
}

// Scratch (device globals: allocation-free rule)
__device__ __nv_bfloat16 g_A[POST_N * KDIM];   // out_spikes^T bf16 [post][k]
__device__ __nv_bfloat16 g_B[PRE_N * KDIM];    // trace_pre^T bf16 [pre][k]
__device__ float g_spart[BATCH * POST_N];

// ---------------------------------------------------------------------------
// Combined preprocess (one launch, 2 columns per thread, float2 loads):
//  blocks [0, NB_PRE)             : trace_pre scan -> g_B (K-major bf16)
//  blocks [NB_PRE, NB_PRE+NB_POST): out_spikes^T   -> g_A + s partials
// ---------------------------------------------------------------------------
__global__ void __launch_bounds__(256) prep_kernel(
    const float* __restrict__ in_spikes, const float* __restrict__ out_spikes)
{
    if (blockIdx.x < NB_PRE) {
        int g = blockIdx.x * 256 + threadIdx.x;          // column-pair index
        int pv = g & (PRE_N / 2 - 1);                    // 0..2047
        int b  = g / (PRE_N / 2);                        // 0..15
        const int p0 = 2 * pv;
        const float2* src = reinterpret_cast<const float2*>(
            in_spikes + (size_t)b * PRE_N + p0);
        float tp0 = 0.0f, tp1 = 0.0f;
        unsigned int pk0[T_STEPS / 2], pk1[T_STEPS / 2];
#pragma unroll
        for (int t2 = 0; t2 < T_STEPS / 2; ++t2) {
            float2 ia = src[(size_t)(2 * t2)     * (BATCH * PRE_N / 2)];
            float2 ib = src[(size_t)(2 * t2 + 1) * (BATCH * PRE_N / 2)];
            tp0 = fminf(fmaxf(fmaf(0.5f, tp0, ia.x), 0.0f), 1.0f);
            float v00 = tp0;
            tp1 = fminf(fmaxf(fmaf(0.5f, tp1, ia.y), 0.0f), 1.0f);
            float v10 = tp1;
            tp0 = fminf(fmaxf(fmaf(0.5f, tp0, ib.x), 0.0f), 1.0f);
            float v01 = tp0;
            tp1 = fminf(fmaxf(fmaf(0.5f, tp1, ib.y), 0.0f), 1.0f);
            float v11 = tp1;
            __nv_bfloat162 h0 = __floats2bfloat162_rn(v00, v01);
            __nv_bfloat162 h1 = __floats2bfloat162_rn(v10, v11);
            pk0[t2] = *reinterpret_cast<unsigned int*>(&h0);
            pk1[t2] = *reinterpret_cast<unsigned int*>(&h1);
        }
        uint4* d0 = reinterpret_cast<uint4*>(g_B + (size_t)p0 * KDIM + b * T_STEPS);
        uint4* d1 = reinterpret_cast<uint4*>(g_B + (size_t)(p0 + 1) * KDIM + b * T_STEPS);
#pragma unroll
        for (int i = 0; i < 8; ++i) {
            d0[i] = make_uint4(pk0[4*i+0], pk0[4*i+1], pk0[4*i+2], pk0[4*i+3]);
            d1[i] = make_uint4(pk1[4*i+0], pk1[4*i+1], pk1[4*i+2], pk1[4*i+3]);
        }
    } else {
        int g = (blockIdx.x - NB_PRE) * 256 + threadIdx.x;
        int qv = g & (POST_N / 2 - 1);
        int b  = g / (POST_N / 2);
        const int q0 = 2 * qv;
        const float2* src = reinterpret_cast<const float2*>(
            out_spikes + (size_t)b * POST_N + q0);
        float tp0 = 0.0f, tp1 = 0.0f, s0 = 0.0f, s1 = 0.0f;
        unsigned int pk0[T_STEPS / 2], pk1[T_STEPS / 2];
#pragma unroll
        for (int t2 = 0; t2 < T_STEPS / 2; ++t2) {
            float2 oa = src[(size_t)(2 * t2)     * (BATCH * POST_N / 2)];
            float2 ob = src[(size_t)(2 * t2 + 1) * (BATCH * POST_N / 2)];
            tp0 = fmaf(0.5f, tp0, oa.x);  s0 = fmaf(oa.x, tp0, s0);
            tp1 = fmaf(0.5f, tp1, oa.y);  s1 = fmaf(oa.y, tp1, s1);
            tp0 = fmaf(0.5f, tp0, ob.x);  s0 = fmaf(ob.x, tp0, s0);
            tp1 = fmaf(0.5f, tp1, ob.y);  s1 = fmaf(ob.y, tp1, s1);
            __nv_bfloat162 h0 = __floats2bfloat162_rn(oa.x, ob.x);
            __nv_bfloat162 h1 = __floats2bfloat162_rn(oa.y, ob.y);
            pk0[t2] = *reinterpret_cast<unsigned int*>(&h0);
            pk1[t2] = *reinterpret_cast<unsigned int*>(&h1);
        }
        uint4* d0 = reinterpret_cast<uint4*>(g_A + (size_t)q0 * KDIM + b * T_STEPS);
        uint4* d1 = reinterpret_cast<uint4*>(g_A + (size_t)(q0 + 1) * KDIM + b * T_STEPS);
#pragma unroll
        for (int i = 0; i < 8; ++i) {
            d0[i] = make_uint4(pk0[4*i+0], pk0[4*i+1], pk0[4*i+2], pk0[4*i+3]);
            d1[i] = make_uint4(pk1[4*i+0], pk1[4*i+1], pk1[4*i+2], pk1[4*i+3]);
        }
        g_spart[b * POST_N + q0]     = s0;
        g_spart[b * POST_N + q0 + 1] = s1;
    }
}

// ---------------------------------------------------------------------------
// PTX helpers
// ---------------------------------------------------------------------------
__device__ __forceinline__ void cp_async16(unsigned int saddr, const void* gptr) {
    asm volatile("cp.async.cg.shared.global [%0], [%1], 16;"
                 :: "r"(saddr), "l"(gptr) : "memory");
}

__device__ __forceinline__ void l2_prefetch(const void* gptr) {
    asm volatile("prefetch.global.L2 [%0];" :: "l"(gptr));
}

__device__ __forceinline__ void ldsm_x4(unsigned int& r0, unsigned int& r1,
                                        unsigned int& r2, unsigned int& r3,
                                        unsigned int addr) {
    asm volatile("ldmatrix.sync.aligned.m8n8.x4.shared.b16 {%0,%1,%2,%3}, [%4];"
                 : "=r"(r0), "=r"(r1), "=r"(r2), "=r"(r3) : "r"(addr));
}

__device__ __forceinline__ void mma16816(float* c,
                                         unsigned int a0, unsigned int a1,
                                         unsigned int a2, unsigned int a3,
                                         unsigned int b0, unsigned int b1) {
    asm volatile(
        "mma.sync.aligned.m16n8k16.row.col.f32.bf16.bf16.f32 "
        "{%0,%1,%2,%3}, {%4,%5,%6,%7}, {%8,%9}, {%0,%1,%2,%3};"
        : "+f"(c[0]), "+f"(c[1]), "+f"(c[2]), "+f"(c[3])
        : "r"(a0), "r"(a1), "r"(a2), "r"(a3), "r"(b0), "r"(b1));
}

// ---------------------------------------------------------------------------
// GEMM: identical to R13 (best known: 103.5us).
// D[128 x 128] CTA tile, 8 warps (2 M x 4 N), warp tile 64x32, 3-stage
// cp.async pipeline (wait_group 1), 2 CTAs/SM, spread loads, s in smem,
// W L2-prefetch, __ldcs/__stcs epilogue.
// ---------------------------------------------------------------------------
__global__ void __launch_bounds__(256, 2) stdp_gemm_kernel(
    const float* __restrict__ weight, float* __restrict__ out)
{
    extern __shared__ __align__(1024) char smem[];
    const unsigned int sbase = (unsigned int)__cvta_generic_to_shared(smem);
    float* s_sm = reinterpret_cast<float*>(smem + S_OFF);
    const int tid = threadIdx.x;
    const int wid = tid >> 5;
    const int lid = tid & 31;
    const int n0 = blockIdx.x * TN;
    const int m0 = blockIdx.y * TM;

    const int warp_m = wid & 1;   // m offset 0/64
    const int warp_n = wid >> 1;  // n offset 0/32/64/96

    // ---- per-thread load addressing ----
    const int lm = tid >> 3;
    const int k8 = tid & 7;
    const unsigned int sw_base =
        (unsigned int)(lm * 128) + ((unsigned int)(k8 * 16) ^ ((lm & 7) << 4));
    const __nv_bfloat16* pa = g_A + (size_t)(m0 + lm) * KDIM + k8 * 8;
    const __nv_bfloat16* pb = g_B + (size_t)(n0 + lm) * KDIM + k8 * 8;

    auto load_chunk_full = [&](const __nv_bfloat16* a, const __nv_bfloat16* b, int st) {
        const unsigned int sa = sbase + st * STAGE_BYTES + sw_base;
#pragma unroll
        for (int i = 0; i < 4; ++i)
            cp_async16(sa + i * 4096, a + (size_t)i * 32 * KDIM);
        const unsigned int sb = sa + A_STAGE_BYTES;
#pragma unroll
        for (int i = 0; i < 4; ++i)
            cp_async16(sb + i * 4096, b + (size_t)i * 32 * KDIM);
    };

    // ---- ldmatrix lane addressing ----
    const int q  = lid >> 3;
    const int r  = lid & 7;
    const int lrow = (q & 1) * 8 + r;
    const int lkb  = (q >> 1) * 16;
    unsigned int kxor[4];
#pragma unroll
    for (int ks = 0; ks < 4; ++ks)
        kxor[ks] = (unsigned int)((ks * 32 + lkb) ^ (r << 4));
    const unsigned int a_rowbase = (unsigned int)((warp_m * 64 + lrow) * 128);
    const unsigned int b_rowbase = (unsigned int)((warp_n * 32 + lrow) * 128);

    float acc[4][4][4];
#pragma unroll
    for (int mt = 0; mt < 4; ++mt)
#pragma unroll
        for (int nt = 0; nt < 4; ++nt)
#pragma unroll
            for (int j = 0; j < 4; ++j) acc[mt][nt][j] = 0.0f;

    // ---- prologue: chunks 0,1 -> stages 0,1 ----
    load_chunk_full(pa, pb, 0);
    asm volatile("cp.async.commit_group;" ::: "memory");
    load_chunk_full(pa + KC, pb + KC, 1);
    asm volatile("cp.async.commit_group;" ::: "memory");
    pa += 2 * KC; pb += 2 * KC;   // point at chunk 2 (next prefetch)

    // ---- prologue: reduce this CTA's s[128] into smem (overlaps load wait) ----
    if (tid < TM) {
        float sv = 0.0f;
#pragma unroll
        for (int b = 0; b < BATCH; ++b) sv += __ldg(&g_spart[b * POST_N + m0 + tid]);
        s_sm[tid] = sv;
    }

    // W prefetch base for this warp's epilogue region (64 rows x 1 line)
    const float* wpf = weight + (size_t)(m0 + warp_m * 64) * PRE_N + n0 + warp_n * 32;

    int st = 0;
    // ---- mainloop ----
    for (int c = 0; c < NCHUNK; ++c) {
        asm volatile("cp.async.wait_group 1;" ::: "memory");
        __syncthreads();   // chunk c visible; all warps done with stage st2
                           // (also publishes s_sm before the epilogue)

        const unsigned int sa = sbase + st * STAGE_BYTES;
        const unsigned int sb = sa + A_STAGE_BYTES;
        int st2 = st + 2; if (st2 >= NSTAGES) st2 -= NSTAGES;   // stage for c+2
        const unsigned int spa = sbase + st2 * STAGE_BYTES + sw_base;
        const unsigned int spb = spa + A_STAGE_BYTES;
        const bool do_load = (c + 2 < NCHUNK);

        // L2-prefetch 4 rows of this warp's W epilogue tile per chunk
        if (lid < 4)
            l2_prefetch(wpf + (size_t)(c * 4 + lid) * PRE_N);

#pragma unroll
        for (int ks = 0; ks < 4; ++ks) {
            unsigned int af[4][4], bf[2][4];
#pragma unroll
            for (int mt = 0; mt < 4; ++mt)
                ldsm_x4(af[mt][0], af[mt][1], af[mt][2], af[mt][3],
                        sa + a_rowbase + mt * 2048 + kxor[ks]);
#pragma unroll
            for (int nt2 = 0; nt2 < 2; ++nt2)
                ldsm_x4(bf[nt2][0], bf[nt2][1], bf[nt2][2], bf[nt2][3],
                        sb + b_rowbase + nt2 * 2048 + kxor[ks]);

            // spread chunk-(c+2) loads: 2 cp.asyncs per ks
            if (do_load) {
                if (ks == 0) {
                    cp_async16(spa,        pa);
                    cp_async16(spa + 4096, pa + (size_t)32 * KDIM);
                } else if (ks == 1) {
                    cp_async16(spa + 8192,  pa + (size_t)64 * KDIM);
                    cp_async16(spa + 12288, pa + (size_t)96 * KDIM);
                } else if (ks == 2) {
                    cp_async16(spb,        pb);
                    cp_async16(spb + 4096, pb + (size_t)32 * KDIM);
                } else {
                    cp_async16(spb + 8192,  pb + (size_t)64 * KDIM);
                    cp_async16(spb + 12288, pb + (size_t)96 * KDIM);
                }
            }

#pragma unroll
            for (int mt = 0; mt < 4; ++mt)
#pragma unroll
                for (int nt2 = 0; nt2 < 2; ++nt2) {
                    mma16816(acc[mt][2 * nt2],
                             af[mt][0], af[mt][1], af[mt][2], af[mt][3],
                             bf[nt2][0], bf[nt2][2]);
                    mma16816(acc[mt][2 * nt2 + 1],
                             af[mt][0], af[mt][1], af[mt][2], af[mt][3],
                             bf[nt2][1], bf[nt2][3]);
                }
        }
        asm volatile("cp.async.commit_group;" ::: "memory");
        pa += KC; pb += KC;
        if (++st == NSTAGES) st = 0;
    }

    // ---- fused epilogue: out = acc - s[m] * W[m][n]; s from smem ----
    const int tid4 = lid >> 2;
    const int tp   = lid & 3;
#pragma unroll
    for (int mt = 0; mt < 4; ++mt) {
#pragma unroll
        for (int half = 0; half < 2; ++half) {
            const int lrow_ep = warp_m * 64 + mt * 16 + half * 8 + tid4;
            const int gm = m0 + lrow_ep;
            const float sv = s_sm[lrow_ep];
            const float* wrow = weight + (size_t)gm * PRE_N + n0 + warp_n * 32;
            float* orow       = out    + (size_t)gm * PRE_N + n0 + warp_n * 32;
#pragma unroll
            for (int nt = 0; nt < 4; ++nt) {
                const int col = nt * 8 + 2 * tp;
                float2 w2 = __ldcs(reinterpret_cast<const float2*>(wrow + col));
                float2 o2;
                o2.x = acc[mt][nt][2 * half + 0] - sv * w2.x;
                o2.y = acc[mt][nt][2 * half + 1] - sv * w2.y;
                __stcs(reinterpret_cast<float2*>(orow + col), o2);
            }
        }
    }
}

// ---------------------------------------------------------------------------
extern "C" void kernel_launch(void* const* d_in, const int* in_sizes, int n_in,
                              void* d_out, int out_size) {
    (void)in_sizes; (void)n_in; (void)out_size;
    const float* in_spikes  = (const float*)d_in[0];
    const float* out_spikes = (const float*)d_in[1];
    const float* weight     = (const float*)d_in[2];
    float* out = (float*)d_out;

    cudaFuncSetAttribute(stdp_gemm_kernel,
                         cudaFuncAttributeMaxDynamicSharedMemorySize, SMEM_TOTAL);

    prep_kernel<<<NB_PRE + NB_POST, 256>>>(in_spikes, out_spikes);

    dim3 grid(PRE_N / TN, POST_N / TM);
    stdp_gemm_kernel<<<grid, 256, SMEM_TOTAL>>>(weight, out);
}

// round 17
// speedup vs baseline: 1.1692x; 1.0145x over previous
#include <cuda_runtime.h>
#include <cuda_bf16.h>
#include <cstdint>
#include <cstddef>

// ---------------------------------------------------------------------------
// STDP delta_w:
//   delta_w = sum_t O_t^T P_t  -  s[:,None] * W
// GEMM: K = T*B = 1024, M = POST = 4096, N = PRE = 4096, HMMA mma.sync bf16.
// R17: GEMM byte-identical to R13 (proven best; all 7 structural variants
// regressed or tied). Prep fixed for OCCUPANCY, not vectorization: packed
// state halved via two half-passes (pk[16] reused; store 64B after t=31 and
// after t=63) + __launch_bounds__(256,4) -> >=4 blocks/SM -> single wave.
// R16 evidence: 2-col prep (64 packed regs) regressed; prep is wave-bound.
// ---------------------------------------------------------------------------

namespace {
constexpr int T_STEPS = 64;
constexpr int BATCH   = 16;
constexpr int PRE_N   = 4096;
constexpr int POST_N  = 4096;
constexpr int KDIM    = T_STEPS * BATCH;  // 1024

constexpr int TM = 128;
constexpr int TN = 128;
constexpr int KC = 64;                       // K elems per chunk (128 B rows)
constexpr int NCHUNK  = KDIM / KC;           // 16
constexpr int NSTAGES = 3;
constexpr int A_STAGE_BYTES = TM * 128;      // 16384
constexpr int B_STAGE_BYTES = TN * 128;      // 16384
constexpr int STAGE_BYTES   = A_STAGE_BYTES + B_STAGE_BYTES;   // 32768
constexpr int S_OFF         = NSTAGES * STAGE_BYTES;           // 98304
constexpr int SMEM_TOTAL    = S_OFF + TM * 4;                  // +512 for s[]

constexpr int NB_PRE  = (BATCH * PRE_N)  / 256;  // 256
constexpr int NB_POST = (BATCH * POST_N) / 256;  // 256
}

// Scratch (device globals: allocation-free rule)
__device__ __nv_bfloat16 g_A[POST_N * KDIM];   // out_spikes^T bf16 [post][k]
__device__ __nv_bfloat16 g_B[PRE_N * KDIM];    // trace_pre^T bf16 [pre][k]
__device__ float g_spart[BATCH * POST_N];

// ---------------------------------------------------------------------------
// Combined preprocess (one launch), register-lean two-half-pass stores:
//  blocks [0, NB_PRE)             : trace_pre scan -> g_B (K-major bf16)
//  blocks [NB_PRE, NB_PRE+NB_POST): out_spikes^T   -> g_A + s partials
// ---------------------------------------------------------------------------
__global__ void __launch_bounds__(256, 4) prep_kernel(
    const float* __restrict__ in_spikes, const float* __restrict__ out_spikes)
{
    if (blockIdx.x < NB_PRE) {
        int g = blockIdx.x * 256 + threadIdx.x;
        int p = g & (PRE_N - 1);
        int b = g >> 12;
        const float* src = in_spikes + (size_t)b * PRE_N + p;
        uint4* dst = reinterpret_cast<uint4*>(g_B + (size_t)p * KDIM + b * T_STEPS);
        float tp = 0.0f;
        unsigned int pk[16];
#pragma unroll
        for (int half = 0; half < 2; ++half) {
#pragma unroll
            for (int t2 = 0; t2 < 16; ++t2) {
                const int t = half * 32 + 2 * t2;
                float i0 = src[(size_t)t       * (BATCH * PRE_N)];
                float i1 = src[(size_t)(t + 1) * (BATCH * PRE_N)];
                tp = fminf(fmaxf(fmaf(0.5f, tp, i0), 0.0f), 1.0f);
                float v0 = tp;
                tp = fminf(fmaxf(fmaf(0.5f, tp, i1), 0.0f), 1.0f);
                float v1 = tp;
                __nv_bfloat162 h2 = __floats2bfloat162_rn(v0, v1);
                pk[t2] = *reinterpret_cast<unsigned int*>(&h2);
            }
#pragma unroll
            for (int i = 0; i < 4; ++i)
                dst[half * 4 + i] =
                    make_uint4(pk[4*i+0], pk[4*i+1], pk[4*i+2], pk[4*i+3]);
        }
    } else {
        int g = (blockIdx.x - NB_PRE) * 256 + threadIdx.x;
        int q = g & (POST_N - 1);
        int b = g >> 12;
        const float* src = out_spikes + (size_t)b * POST_N + q;
        uint4* dst = reinterpret_cast<uint4*>(g_A + (size_t)q * KDIM + b * T_STEPS);
        float tp = 0.0f, sacc = 0.0f;
        unsigned int pk[16];
#pragma unroll
        for (int half = 0; half < 2; ++half) {
#pragma unroll
            for (int t2 = 0; t2 < 16; ++t2) {
                const int t = half * 32 + 2 * t2;
                float o0 = src[(size_t)t       * (BATCH * POST_N)];
                float o1 = src[(size_t)(t + 1) * (BATCH * POST_N)];
                tp = fmaf(0.5f, tp, o0);
                sacc = fmaf(o0, tp, sacc);
                tp = fmaf(0.5f, tp, o1);
                sacc = fmaf(o1, tp, sacc);
                __nv_bfloat162 h2 = __floats2bfloat162_rn(o0, o1);
                pk[t2] = *reinterpret_cast<unsigned int*>(&h2);
            }
#pragma unroll
            for (int i = 0; i < 4; ++i)
                dst[half * 4 + i] =
                    make_uint4(pk[4*i+0], pk[4*i+1], pk[4*i+2], pk[4*i+3]);
        }
        g_spart[b * POST_N + q] = sacc;
    }
}

// ---------------------------------------------------------------------------
// PTX helpers
// ---------------------------------------------------------------------------
__device__ __forceinline__ void cp_async16(unsigned int saddr, const void* gptr) {
    asm volatile("cp.async.cg.shared.global [%0], [%1], 16;"
                 :: "r"(saddr), "l"(gptr) : "memory");
}

__device__ __forceinline__ void l2_prefetch(const void* gptr) {
    asm volatile("prefetch.global.L2 [%0];" :: "l"(gptr));
}

__device__ __forceinline__ void ldsm_x4(unsigned int& r0, unsigned int& r1,
                                        unsigned int& r2, unsigned int& r3,
                                        unsigned int addr) {
    asm volatile("ldmatrix.sync.aligned.m8n8.x4.shared.b16 {%0,%1,%2,%3}, [%4];"
                 : "=r"(r0), "=r"(r1), "=r"(r2), "=r"(r3) : "r"(addr));
}

__device__ __forceinline__ void mma16816(float* c,
                                         unsigned int a0, unsigned int a1,
                                         unsigned int a2, unsigned int a3,
                                         unsigned int b0, unsigned int b1) {
    asm volatile(
        "mma.sync.aligned.m16n8k16.row.col.f32.bf16.bf16.f32 "
        "{%0,%1,%2,%3}, {%4,%5,%6,%7}, {%8,%9}, {%0,%1,%2,%3};"
        : "+f"(c[0]), "+f"(c[1]), "+f"(c[2]), "+f"(c[3])
        : "r"(a0), "r"(a1), "r"(a2), "r"(a3), "r"(b0), "r"(b1));
}

// ---------------------------------------------------------------------------
// GEMM: identical to R13 (best known: 103.5us).
// D[128 x 128] CTA tile, 8 warps (2 M x 4 N), warp tile 64x32, 3-stage
// cp.async pipeline (wait_group 1), 2 CTAs/SM, spread loads, s in smem,
// W L2-prefetch, __ldcs/__stcs epilogue.
// ---------------------------------------------------------------------------
__global__ void __launch_bounds__(256, 2) stdp_gemm_kernel(
    const float* __restrict__ weight, float* __restrict__ out)
{
    extern __shared__ __align__(1024) char smem[];
    const unsigned int sbase = (unsigned int)__cvta_generic_to_shared(smem);
    float* s_sm = reinterpret_cast<float*>(smem + S_OFF);
    const int tid = threadIdx.x;
    const int wid = tid >> 5;
    const int lid = tid & 31;
    const int n0 = blockIdx.x * TN;
    const int m0 = blockIdx.y * TM;

    const int warp_m = wid & 1;   // m offset 0/64
    const int warp_n = wid >> 1;  // n offset 0/32/64/96

    // ---- per-thread load addressing ----
    const int lm = tid >> 3;
    const int k8 = tid & 7;
    const unsigned int sw_base =
        (unsigned int)(lm * 128) + ((unsigned int)(k8 * 16) ^ ((lm & 7) << 4));
    const __nv_bfloat16* pa = g_A + (size_t)(m0 + lm) * KDIM + k8 * 8;
    const __nv_bfloat16* pb = g_B + (size_t)(n0 + lm) * KDIM + k8 * 8;

    auto load_chunk_full = [&](const __nv_bfloat16* a, const __nv_bfloat16* b, int st) {
        const unsigned int sa = sbase + st * STAGE_BYTES + sw_base;
#pragma unroll
        for (int i = 0; i < 4; ++i)
            cp_async16(sa + i * 4096, a + (size_t)i * 32 * KDIM);
        const unsigned int sb = sa + A_STAGE_BYTES;
#pragma unroll
        for (int i = 0; i < 4; ++i)
            cp_async16(sb + i * 4096, b + (size_t)i * 32 * KDIM);
    };

    // ---- ldmatrix lane addressing ----
    const int q  = lid >> 3;
    const int r  = lid & 7;
    const int lrow = (q & 1) * 8 + r;
    const int lkb  = (q >> 1) * 16;
    unsigned int kxor[4];
#pragma unroll
    for (int ks = 0; ks < 4; ++ks)
        kxor[ks] = (unsigned int)((ks * 32 + lkb) ^ (r << 4));
    const unsigned int a_rowbase = (unsigned int)((warp_m * 64 + lrow) * 128);
    const unsigned int b_rowbase = (unsigned int)((warp_n * 32 + lrow) * 128);

    float acc[4][4][4];
#pragma unroll
    for (int mt = 0; mt < 4; ++mt)
#pragma unroll
        for (int nt = 0; nt < 4; ++nt)
#pragma unroll
            for (int j = 0; j < 4; ++j) acc[mt][nt][j] = 0.0f;

    // ---- prologue: chunks 0,1 -> stages 0,1 ----
    load_chunk_full(pa, pb, 0);
    asm volatile("cp.async.commit_group;" ::: "memory");
    load_chunk_full(pa + KC, pb + KC, 1);
    asm volatile("cp.async.commit_group;" ::: "memory");
    pa += 2 * KC; pb += 2 * KC;   // point at chunk 2 (next prefetch)

    // ---- prologue: reduce this CTA's s[128] into smem (overlaps load wait) ----
    if (tid < TM) {
        float sv = 0.0f;
#pragma unroll
        for (int b = 0; b < BATCH; ++b) sv += __ldg(&g_spart[b * POST_N + m0 + tid]);
        s_sm[tid] = sv;
    }

    // W prefetch base for this warp's epilogue region (64 rows x 1 line)
    const float* wpf = weight + (size_t)(m0 + warp_m * 64) * PRE_N + n0 + warp_n * 32;

    int st = 0;
    // ---- mainloop ----
    for (int c = 0; c < NCHUNK; ++c) {
        asm volatile("cp.async.wait_group 1;" ::: "memory");
        __syncthreads();   // chunk c visible; all warps done with stage st2
                           // (also publishes s_sm before the epilogue)

        const unsigned int sa = sbase + st * STAGE_BYTES;
        const unsigned int sb = sa + A_STAGE_BYTES;
        int st2 = st + 2; if (st2 >= NSTAGES) st2 -= NSTAGES;   // stage for c+2
        const unsigned int spa = sbase + st2 * STAGE_BYTES + sw_base;
        const unsigned int spb = spa + A_STAGE_BYTES;
        const bool do_load = (c + 2 < NCHUNK);

        // L2-prefetch 4 rows of this warp's W epilogue tile per chunk
        if (lid < 4)
            l2_prefetch(wpf + (size_t)(c * 4 + lid) * PRE_N);

#pragma unroll
        for (int ks = 0; ks < 4; ++ks) {
            unsigned int af[4][4], bf[2][4];
#pragma unroll
            for (int mt = 0; mt < 4; ++mt)
                ldsm_x4(af[mt][0], af[mt][1], af[mt][2], af[mt][3],
                        sa + a_rowbase + mt * 2048 + kxor[ks]);
#pragma unroll
            for (int nt2 = 0; nt2 < 2; ++nt2)
                ldsm_x4(bf[nt2][0], bf[nt2][1], bf[nt2][2], bf[nt2][3],
                        sb + b_rowbase + nt2 * 2048 + kxor[ks]);

            // spread chunk-(c+2) loads: 2 cp.asyncs per ks
            if (do_load) {
                if (ks == 0) {
                    cp_async16(spa,        pa);
                    cp_async16(spa + 4096, pa + (size_t)32 * KDIM);
                } else if (ks == 1) {
                    cp_async16(spa + 8192,  pa + (size_t)64 * KDIM);
                    cp_async16(spa + 12288, pa + (size_t)96 * KDIM);
                } else if (ks == 2) {
                    cp_async16(spb,        pb);
                    cp_async16(spb + 4096, pb + (size_t)32 * KDIM);
                } else {
                    cp_async16(spb + 8192,  pb + (size_t)64 * KDIM);
                    cp_async16(spb + 12288, pb + (size_t)96 * KDIM);
                }
            }

#pragma unroll
            for (int mt = 0; mt < 4; ++mt)
#pragma unroll
                for (int nt2 = 0; nt2 < 2; ++nt2) {
                    mma16816(acc[mt][2 * nt2],
                             af[mt][0], af[mt][1], af[mt][2], af[mt][3],
                             bf[nt2][0], bf[nt2][2]);
                    mma16816(acc[mt][2 * nt2 + 1],
                             af[mt][0], af[mt][1], af[mt][2], af[mt][3],
                             bf[nt2][1], bf[nt2][3]);
                }
        }
        asm volatile("cp.async.commit_group;" ::: "memory");
        pa += KC; pb += KC;
        if (++st == NSTAGES) st = 0;
    }

    // ---- fused epilogue: out = acc - s[m] * W[m][n]; s from smem ----
    const int tid4 = lid >> 2;
    const int tp   = lid & 3;
#pragma unroll
    for (int mt = 0; mt < 4; ++mt) {
#pragma unroll
        for (int half = 0; half < 2; ++half) {
            const int lrow_ep = warp_m * 64 + mt * 16 + half * 8 + tid4;
            const int gm = m0 + lrow_ep;
            const float sv = s_sm[lrow_ep];
            const float* wrow = weight + (size_t)gm * PRE_N + n0 + warp_n * 32;
            float* orow       = out    + (size_t)gm * PRE_N + n0 + warp_n * 32;
#pragma unroll
            for (int nt = 0; nt < 4; ++nt) {
                const int col = nt * 8 + 2 * tp;
                float2 w2 = __ldcs(reinterpret_cast<const float2*>(wrow + col));
                float2 o2;
                o2.x = acc[mt][nt][2 * half + 0] - sv * w2.x;
                o2.y = acc[mt][nt][2 * half + 1] - sv * w2.y;
                __stcs(reinterpret_cast<float2*>(orow + col), o2);
            }
        }
    }
}

// ---------------------------------------------------------------------------
extern "C" void kernel_launch(void* const* d_in, const int* in_sizes, int n_in,
                              void* d_out, int out_size) {
    (void)in_sizes; (void)n_in; (void)out_size;
    const float* in_spikes  = (const float*)d_in[0];
    const float* out_spikes = (const float*)d_in[1];
    const float* weight     = (const float*)d_in[2];
    float* out = (float*)d_out;

    cudaFuncSetAttribute(stdp_gemm_kernel,
                         cudaFuncAttributeMaxDynamicSharedMemorySize, SMEM_TOTAL);

    prep_kernel<<<NB_PRE + NB_POST, 256>>>(in_spikes, out_spikes);

    dim3 grid(PRE_N / TN, POST_N / TM);
    stdp_gemm_kernel<<<grid, 256, SMEM_TOTAL>>>(weight, out);
}